// round 8
// baseline (speedup 1.0000x reference)
#include <cuda_runtime.h>
#include <math.h>
#include <stdint.h>

#define H 4096
#define V 4
#define MS 104
#define MD 3
#define OUT 4
#define GRID_GRU 1024   // H/4 blocks, 4 warps, 1 hidden unit per warp
#define B_RES 512       // blocks [0,B_RES): evict_last loads -> protected L2 set (~98 MB)

// scratch (device globals are the allowed scratch mechanism)
__device__ float g_hbar[H];
__device__ float g_dots[9];            // zero at load; finale resets -> clean each replay
__device__ unsigned int g_count = 0;   // last-block detector; finale resets

__device__ __forceinline__ float sigmoidf_(float x) {
    return 1.0f / (1.0f + expf(-x));
}

// 32-byte evict_last load (sm_103a requires .v8.b32/.v4.b64 width for this hint)
__device__ __forceinline__ void ld_resident32B(const void* p, float4& lo, float4& hi) {
    unsigned long long a, b, c, d;
    asm("ld.global.L2::evict_last.v4.b64 {%0,%1,%2,%3}, [%4];"
        : "=l"(a), "=l"(b), "=l"(c), "=l"(d) : "l"(p));
    lo.x = __uint_as_float((unsigned)a);  lo.y = __uint_as_float((unsigned)(a >> 32));
    lo.z = __uint_as_float((unsigned)b);  lo.w = __uint_as_float((unsigned)(b >> 32));
    hi.x = __uint_as_float((unsigned)c);  hi.y = __uint_as_float((unsigned)(c >> 32));
    hi.z = __uint_as_float((unsigned)d);  hi.w = __uint_as_float((unsigned)(d >> 32));
}

// ---------------------------------------------------------------------------
// Kernel 1: h_bar = w_sh @ stack[0] + b_sh + hidden0 (float4-vectorized)
// ---------------------------------------------------------------------------
__global__ void k_hbar(const float* __restrict__ w_sh,
                       const float* __restrict__ b_sh,
                       const float* __restrict__ hidden0,
                       const float* __restrict__ stack) {
    int t = blockIdx.x * blockDim.x + threadIdx.x;   // 0..1023
    const float4* w4  = reinterpret_cast<const float4*>(w_sh);
    const float4* b4p = reinterpret_cast<const float4*>(b_sh);
    const float4* h4p = reinterpret_cast<const float4*>(hidden0);

    float s0 = stack[0], s1 = stack[1], s2 = stack[2];
    float4 a = w4[3 * t + 0];
    float4 b = w4[3 * t + 1];
    float4 c = w4[3 * t + 2];
    float4 bb = b4p[t];
    float4 h0 = h4p[t];

    float4 r;
    r.x = fmaf(a.x, s0, fmaf(a.y, s1, fmaf(a.z, s2, bb.x + h0.x)));
    r.y = fmaf(a.w, s0, fmaf(b.x, s1, fmaf(b.y, s2, bb.y + h0.y)));
    r.z = fmaf(b.z, s0, fmaf(b.w, s1, fmaf(c.x, s2, bb.z + h0.z)));
    r.w = fmaf(c.y, s0, fmaf(c.z, s1, fmaf(c.w, s2, bb.w + h0.w)));
    reinterpret_cast<float4*>(g_hbar)[t] = r;
}

__device__ __forceinline__ float dot4(float4 a, float4 b, float acc) {
    return fmaf(a.x, b.x, fmaf(a.y, b.y, fmaf(a.z, b.z, fmaf(a.w, b.w, acc))));
}

// resident mainloop: 32-byte evict_last loads, 16 iterations per row
__device__ __forceinline__ void gru_dots_resident(const float* __restrict__ wr,
                                                  const float* __restrict__ wz,
                                                  const float* __restrict__ wn,
                                                  const float4* __restrict__ s4,
                                                  int lane,
                                                  float& ar, float& az, float& an) {
    #pragma unroll 4
    for (int k = lane; k < H / 8; k += 32) {     // k indexes 32-byte chunks
        float4 hlo = s4[2 * k], hhi = s4[2 * k + 1];
        float4 rlo, rhi, zlo, zhi, nlo, nhi;
        ld_resident32B(wr + 8 * k, rlo, rhi);
        ld_resident32B(wz + 8 * k, zlo, zhi);
        ld_resident32B(wn + 8 * k, nlo, nhi);
        ar = dot4(rhi, hhi, dot4(rlo, hlo, ar));
        az = dot4(zhi, hhi, dot4(zlo, hlo, az));
        an = dot4(nhi, hhi, dot4(nlo, hlo, an));
    }
}

// streaming mainloop: __ldcs float4 (evict-first), as in R2/R4
__device__ __forceinline__ void gru_dots_stream(const float4* __restrict__ wr,
                                                const float4* __restrict__ wz,
                                                const float4* __restrict__ wn,
                                                const float4* __restrict__ s4,
                                                int lane,
                                                float& ar, float& az, float& an) {
    #pragma unroll 4
    for (int k = lane; k < H / 4; k += 32) {
        float4 h4 = s4[k];
        ar = dot4(__ldcs(wr + k), h4, ar);
        az = dot4(__ldcs(wz + k), h4, az);
        an = dot4(__ldcs(wn + k), h4, an);
    }
}

// ---------------------------------------------------------------------------
// Kernel 2: heavy matvec + GRU gates + fused heads + last-block finale.
// ---------------------------------------------------------------------------
__global__ void __launch_bounds__(128, 8)
k_gru(const float* __restrict__ w_hh,
      const float* __restrict__ w_ih,
      const float* __restrict__ b_ih,
      const float* __restrict__ b_hh,
      const float* __restrict__ emb,
      const int*   __restrict__ inp,
      const float* __restrict__ w_y,
      const float* __restrict__ b_y,
      const float* __restrict__ w_n,
      const float* __restrict__ b_n,
      const float* __restrict__ w_a,
      const float* __restrict__ b_a,
      const float* __restrict__ stack,
      float* __restrict__ out) {
    __shared__ float sh_hbar[H];
    __shared__ float sx[V];
    __shared__ float sh_h[4];
    __shared__ float sh_fin[12];   // [0..8]=dots+bias, [9]=a0, [10]=a1, [11]=is_last

    const int tid = threadIdx.x;

    // stage h_bar into shared (coalesced float4)
    const float4* hb4 = reinterpret_cast<const float4*>(g_hbar);
    float4* sw = reinterpret_cast<float4*>(sh_hbar);
    #pragma unroll
    for (int j = tid; j < H / 4; j += 128) sw[j] = hb4[j];
    if (tid < V) sx[tid] = emb[inp[0] * V + tid];
    if (tid == 0) sh_fin[11] = 0.0f;
    __syncthreads();
    const float4* s4 = reinterpret_cast<const float4*>(sh_hbar);

    const int warp = tid >> 5;
    const int lane = tid & 31;
    const int i = blockIdx.x * 4 + warp;   // hidden unit

    const float* wr = w_hh + (size_t)i          * H;
    const float* wz = w_hh + (size_t)(i + H)    * H;
    const float* wn = w_hh + (size_t)(i + 2*H)  * H;

    float ar = 0.f, az = 0.f, an = 0.f;
    if (blockIdx.x < B_RES)
        gru_dots_resident(wr, wz, wn, s4, lane, ar, az, an);     // protected L2 set
    else
        gru_dots_stream(reinterpret_cast<const float4*>(wr),
                        reinterpret_cast<const float4*>(wz),
                        reinterpret_cast<const float4*>(wn),
                        s4, lane, ar, az, an);                   // streaming set

    #pragma unroll
    for (int o = 16; o > 0; o >>= 1) {
        ar += __shfl_xor_sync(0xFFFFFFFFu, ar, o);
        az += __shfl_xor_sync(0xFFFFFFFFu, az, o);
        an += __shfl_xor_sync(0xFFFFFFFFu, an, o);
    }

    if (lane == 0) {
        const float x0 = sx[0], x1 = sx[1], x2 = sx[2], x3 = sx[3];
        const float* wir = w_ih + (size_t)i * V;
        const float* wiz = w_ih + (size_t)(i + H) * V;
        const float* win = w_ih + (size_t)(i + 2*H) * V;
        float gir = fmaf(wir[0], x0, fmaf(wir[1], x1, fmaf(wir[2], x2, fmaf(wir[3], x3, b_ih[i]))));
        float giz = fmaf(wiz[0], x0, fmaf(wiz[1], x1, fmaf(wiz[2], x2, fmaf(wiz[3], x3, b_ih[i + H]))));
        float gin = fmaf(win[0], x0, fmaf(win[1], x1, fmaf(win[2], x2, fmaf(win[3], x3, b_ih[i + 2*H]))));

        float r = sigmoidf_(gir + ar + b_hh[i]);
        float z = sigmoidf_(giz + az + b_hh[i + H]);
        float n = tanhf(gin + (an + b_hh[i + 2*H]) * r);
        float hb = sh_hbar[i];
        float h = (1.0f - z) * n + z * hb;
        out[OUT + i] = h;
        sh_h[warp] = h;
    }
    __syncthreads();

    // head contributions: threads 0..8, one head each; rows i0..i0+3 are one float4
    if (tid < 9) {
        const int i0 = blockIdx.x * 4;
        const float* w = (tid < 4) ? (w_y + (size_t)tid * H)
                       : (tid < 6) ? (w_a + (size_t)(tid - 4) * H)
                                   : (w_n + (size_t)(tid - 6) * H);
        float4 wv = *reinterpret_cast<const float4*>(w + i0);
        float acc = fmaf(wv.x, sh_h[0], fmaf(wv.y, sh_h[1],
                    fmaf(wv.z, sh_h[2], wv.w * sh_h[3])));
        atomicAdd(&g_dots[tid], acc);
    }

    // last-block detection
    if (tid == 0) {
        __threadfence();
        unsigned int old = atomicAdd(&g_count, 1u);
        if (old == GRID_GRU - 1) sh_fin[11] = 1.0f;
    }
    __syncthreads();
    if (sh_fin[11] == 0.0f) return;

    // ---- finale (last block only) ----
    if (tid < 9) {
        float d = atomicExch(&g_dots[tid], 0.0f);   // read + reset for next replay
        float bias = (tid < 4) ? b_y[tid] : (tid < 6) ? b_a[tid - 4] : b_n[tid - 6];
        sh_fin[tid] = d + bias;
    }
    if (tid == 32) atomicExch(&g_count, 0u);        // reset detector
    __syncthreads();

    if (tid == 0) {
        out[0] = sigmoidf_(sh_fin[0]);
        out[1] = sigmoidf_(sh_fin[1]);
        out[2] = sigmoidf_(sh_fin[2]);
        out[3] = sigmoidf_(sh_fin[3]);
        float m  = fmaxf(sh_fin[4], sh_fin[5]);
        float e0 = expf(sh_fin[4] - m);
        float e1 = expf(sh_fin[5] - m);
        float inv = 1.0f / (e0 + e1);
        sh_fin[9]  = e0 * inv;
        sh_fin[10] = e1 * inv;
    }
    __syncthreads();

    const float a0 = sh_fin[9];
    const float a1 = sh_fin[10];
    for (int idx = tid; idx < MS * MD; idx += 128) {
        int r = idx / MD;
        int m = idx - r * MD;
        float push = (r == 0)      ? sigmoidf_(sh_fin[6 + m]) : stack[(r - 1) * MD + m];
        float pop  = (r == MS - 1) ? 0.0f                     : stack[(r + 1) * MD + m];
        out[OUT + H + idx] = fmaf(a0, push, a1 * pop);
    }
}

// ---------------------------------------------------------------------------
// Launch. Input order: inp, hidden0, stack, emb, w_ih, w_hh, b_ih, b_hh,
// w_y, b_y, w_n, b_n, w_a, b_a, w_sh, b_sh.
// Output: [output(4) | hidden(4096) | new_stack(312)] f32.
// ---------------------------------------------------------------------------
extern "C" void kernel_launch(void* const* d_in, const int* in_sizes, int n_in,
                              void* d_out, int out_size) {
    const int*   inp     = (const int*)  d_in[0];
    const float* hidden0 = (const float*)d_in[1];
    const float* stack   = (const float*)d_in[2];
    const float* emb     = (const float*)d_in[3];
    const float* w_ih    = (const float*)d_in[4];
    const float* w_hh    = (const float*)d_in[5];
    const float* b_ih    = (const float*)d_in[6];
    const float* b_hh    = (const float*)d_in[7];
    const float* w_y     = (const float*)d_in[8];
    const float* b_y     = (const float*)d_in[9];
    const float* w_n     = (const float*)d_in[10];
    const float* b_n     = (const float*)d_in[11];
    const float* w_a     = (const float*)d_in[12];
    const float* b_a     = (const float*)d_in[13];
    const float* w_sh    = (const float*)d_in[14];
    const float* b_sh    = (const float*)d_in[15];
    float* out = (float*)d_out;

    k_hbar<<<4, 256>>>(w_sh, b_sh, hidden0, stack);
    k_gru<<<GRID_GRU, 128>>>(w_hh, w_ih, b_ih, b_hh, emb, inp,
                             w_y, b_y, w_n, b_n, w_a, b_a, stack, out);
}

// round 9
// speedup vs baseline: 1.1232x; 1.1232x over previous
#include <cuda_runtime.h>
#include <math.h>
#include <stdint.h>

#define H 4096
#define V 4
#define MS 104
#define MD 3
#define OUT 4
#define GRID_GRU 1024   // H/4 blocks, 4 warps, 1 hidden unit per warp
#define B_RES 448       // blocks [0,B_RES): evict_last loads -> protected L2 set (~86 MB)

// scratch (device globals are the allowed scratch mechanism)
__device__ float g_hbar[H];
__device__ float g_dots[9];                 // zero at load; finale resets -> clean each replay
__device__ unsigned int g_count = 0;        // last-block detector; finale resets
__device__ unsigned int g_hbar_done = 0;    // producer-block counter; finale resets

__device__ __forceinline__ float sigmoidf_(float x) {
    return 1.0f / (1.0f + expf(-x));
}

// 32-byte evict_last load (sm_103a requires .v8.b32/.v4.b64 width for this hint)
__device__ __forceinline__ void ld_resident32B(const void* p, float4& lo, float4& hi) {
    unsigned long long a, b, c, d;
    asm("ld.global.L2::evict_last.v4.b64 {%0,%1,%2,%3}, [%4];"
        : "=l"(a), "=l"(b), "=l"(c), "=l"(d) : "l"(p));
    lo.x = __uint_as_float((unsigned)a);  lo.y = __uint_as_float((unsigned)(a >> 32));
    lo.z = __uint_as_float((unsigned)b);  lo.w = __uint_as_float((unsigned)(b >> 32));
    hi.x = __uint_as_float((unsigned)c);  hi.y = __uint_as_float((unsigned)(c >> 32));
    hi.z = __uint_as_float((unsigned)d);  hi.w = __uint_as_float((unsigned)(d >> 32));
}

__device__ __forceinline__ float dot4(float4 a, float4 b, float acc) {
    return fmaf(a.x, b.x, fmaf(a.y, b.y, fmaf(a.z, b.z, fmaf(a.w, b.w, acc))));
}

// resident mainloop: 32-byte evict_last loads, 16 iterations per row
__device__ __forceinline__ void gru_dots_resident(const float* __restrict__ wr,
                                                  const float* __restrict__ wz,
                                                  const float* __restrict__ wn,
                                                  const float4* __restrict__ s4,
                                                  int lane,
                                                  float& ar, float& az, float& an) {
    #pragma unroll 4
    for (int k = lane; k < H / 8; k += 32) {     // k indexes 32-byte chunks
        float4 hlo = s4[2 * k], hhi = s4[2 * k + 1];
        float4 rlo, rhi, zlo, zhi, nlo, nhi;
        ld_resident32B(wr + 8 * k, rlo, rhi);
        ld_resident32B(wz + 8 * k, zlo, zhi);
        ld_resident32B(wn + 8 * k, nlo, nhi);
        ar = dot4(rhi, hhi, dot4(rlo, hlo, ar));
        az = dot4(zhi, hhi, dot4(zlo, hlo, az));
        an = dot4(nhi, hhi, dot4(nlo, hlo, an));
    }
}

// streaming mainloop: __ldcs float4 (evict-first)
__device__ __forceinline__ void gru_dots_stream(const float4* __restrict__ wr,
                                                const float4* __restrict__ wz,
                                                const float4* __restrict__ wn,
                                                const float4* __restrict__ s4,
                                                int lane,
                                                float& ar, float& az, float& an) {
    #pragma unroll 4
    for (int k = lane; k < H / 4; k += 32) {
        float4 h4 = s4[k];
        ar = dot4(__ldcs(wr + k), h4, ar);
        az = dot4(__ldcs(wz + k), h4, az);
        an = dot4(__ldcs(wn + k), h4, an);
    }
}

// ---------------------------------------------------------------------------
// Single fused kernel: producer blocks compute h_bar, all blocks spin on the
// counter, then heavy matvec + GRU gates + fused heads + last-block finale.
// ---------------------------------------------------------------------------
__global__ void __launch_bounds__(128, 8)
k_gru(const float* __restrict__ w_hh,
      const float* __restrict__ w_ih,
      const float* __restrict__ b_ih,
      const float* __restrict__ b_hh,
      const float* __restrict__ emb,
      const int*   __restrict__ inp,
      const float* __restrict__ w_y,
      const float* __restrict__ b_y,
      const float* __restrict__ w_n,
      const float* __restrict__ b_n,
      const float* __restrict__ w_a,
      const float* __restrict__ b_a,
      const float* __restrict__ stack,
      const float* __restrict__ w_sh,
      const float* __restrict__ b_sh,
      const float* __restrict__ hidden0,
      float* __restrict__ out) {
    __shared__ float sh_hbar[H];
    __shared__ float sx[V];
    __shared__ float sh_h[4];
    __shared__ float sh_fin[12];   // [0..8]=dots+bias, [9]=a0, [10]=a1, [11]=is_last

    const int tid = threadIdx.x;

    // ---- producer phase: blocks 0..3 compute a quarter of g_hbar each ----
    if (blockIdx.x < 4) {
        const float4* w4  = reinterpret_cast<const float4*>(w_sh);
        const float4* b4p = reinterpret_cast<const float4*>(b_sh);
        const float4* h4p = reinterpret_cast<const float4*>(hidden0);
        float s0 = stack[0], s1 = stack[1], s2 = stack[2];
        #pragma unroll
        for (int u = 0; u < 2; ++u) {
            int t = blockIdx.x * 256 + tid + u * 128;   // float4 output index
            float4 a = w4[3 * t + 0];
            float4 b = w4[3 * t + 1];
            float4 c = w4[3 * t + 2];
            float4 bb = b4p[t];
            float4 h0 = h4p[t];
            float4 r;
            r.x = fmaf(a.x, s0, fmaf(a.y, s1, fmaf(a.z, s2, bb.x + h0.x)));
            r.y = fmaf(a.w, s0, fmaf(b.x, s1, fmaf(b.y, s2, bb.y + h0.y)));
            r.z = fmaf(b.z, s0, fmaf(b.w, s1, fmaf(c.x, s2, bb.z + h0.z)));
            r.w = fmaf(c.y, s0, fmaf(c.z, s1, fmaf(c.w, s2, bb.w + h0.w)));
            reinterpret_cast<float4*>(g_hbar)[t] = r;
        }
        __threadfence();
        __syncthreads();
        if (tid == 0) atomicAdd(&g_hbar_done, 1u);
    }

    // ---- all blocks: wait for h_bar to be complete ----
    if (tid == 0) {
        while (*(volatile unsigned int*)&g_hbar_done < 4u) __nanosleep(20);
        sh_fin[11] = 0.0f;
    }
    __syncthreads();

    // stage h_bar into shared (coalesced float4; g_hbar is L2-hot)
    const float4* hb4 = reinterpret_cast<const float4*>(g_hbar);
    float4* sw = reinterpret_cast<float4*>(sh_hbar);
    #pragma unroll
    for (int j = tid; j < H / 4; j += 128) sw[j] = hb4[j];
    if (tid < V) sx[tid] = emb[inp[0] * V + tid];
    __syncthreads();
    const float4* s4 = reinterpret_cast<const float4*>(sh_hbar);

    const int warp = tid >> 5;
    const int lane = tid & 31;
    const int i = blockIdx.x * 4 + warp;   // hidden unit

    const float* wr = w_hh + (size_t)i          * H;
    const float* wz = w_hh + (size_t)(i + H)    * H;
    const float* wn = w_hh + (size_t)(i + 2*H)  * H;

    float ar = 0.f, az = 0.f, an = 0.f;
    if (blockIdx.x < B_RES)
        gru_dots_resident(wr, wz, wn, s4, lane, ar, az, an);     // protected L2 set
    else
        gru_dots_stream(reinterpret_cast<const float4*>(wr),
                        reinterpret_cast<const float4*>(wz),
                        reinterpret_cast<const float4*>(wn),
                        s4, lane, ar, az, an);                   // streaming set

    #pragma unroll
    for (int o = 16; o > 0; o >>= 1) {
        ar += __shfl_xor_sync(0xFFFFFFFFu, ar, o);
        az += __shfl_xor_sync(0xFFFFFFFFu, az, o);
        an += __shfl_xor_sync(0xFFFFFFFFu, an, o);
    }

    if (lane == 0) {
        const float x0 = sx[0], x1 = sx[1], x2 = sx[2], x3 = sx[3];
        const float* wir = w_ih + (size_t)i * V;
        const float* wiz = w_ih + (size_t)(i + H) * V;
        const float* win = w_ih + (size_t)(i + 2*H) * V;
        float gir = fmaf(wir[0], x0, fmaf(wir[1], x1, fmaf(wir[2], x2, fmaf(wir[3], x3, b_ih[i]))));
        float giz = fmaf(wiz[0], x0, fmaf(wiz[1], x1, fmaf(wiz[2], x2, fmaf(wiz[3], x3, b_ih[i + H]))));
        float gin = fmaf(win[0], x0, fmaf(win[1], x1, fmaf(win[2], x2, fmaf(win[3], x3, b_ih[i + 2*H]))));

        float r = sigmoidf_(gir + ar + b_hh[i]);
        float z = sigmoidf_(giz + az + b_hh[i + H]);
        float n = tanhf(gin + (an + b_hh[i + 2*H]) * r);
        float hb = sh_hbar[i];
        float h = (1.0f - z) * n + z * hb;
        out[OUT + i] = h;
        sh_h[warp] = h;
    }
    __syncthreads();

    // head contributions: threads 0..8, one head each; rows i0..i0+3 are one float4
    if (tid < 9) {
        const int i0 = blockIdx.x * 4;
        const float* w = (tid < 4) ? (w_y + (size_t)tid * H)
                       : (tid < 6) ? (w_a + (size_t)(tid - 4) * H)
                                   : (w_n + (size_t)(tid - 6) * H);
        float4 wv = *reinterpret_cast<const float4*>(w + i0);
        float acc = fmaf(wv.x, sh_h[0], fmaf(wv.y, sh_h[1],
                    fmaf(wv.z, sh_h[2], wv.w * sh_h[3])));
        atomicAdd(&g_dots[tid], acc);
    }

    // last-block detection
    if (tid == 0) {
        __threadfence();
        unsigned int old = atomicAdd(&g_count, 1u);
        if (old == GRID_GRU - 1) sh_fin[11] = 1.0f;
    }
    __syncthreads();
    if (sh_fin[11] == 0.0f) return;

    // ---- finale (last block only) ----
    if (tid < 9) {
        float d = atomicExch(&g_dots[tid], 0.0f);   // read + reset for next replay
        float bias = (tid < 4) ? b_y[tid] : (tid < 6) ? b_a[tid - 4] : b_n[tid - 6];
        sh_fin[tid] = d + bias;
    }
    if (tid == 32) atomicExch(&g_count, 0u);        // reset detector
    if (tid == 33) atomicExch(&g_hbar_done, 0u);    // reset producer counter
    __syncthreads();

    if (tid == 0) {
        out[0] = sigmoidf_(sh_fin[0]);
        out[1] = sigmoidf_(sh_fin[1]);
        out[2] = sigmoidf_(sh_fin[2]);
        out[3] = sigmoidf_(sh_fin[3]);
        float m  = fmaxf(sh_fin[4], sh_fin[5]);
        float e0 = expf(sh_fin[4] - m);
        float e1 = expf(sh_fin[5] - m);
        float inv = 1.0f / (e0 + e1);
        sh_fin[9]  = e0 * inv;
        sh_fin[10] = e1 * inv;
    }
    __syncthreads();

    const float a0 = sh_fin[9];
    const float a1 = sh_fin[10];
    for (int idx = tid; idx < MS * MD; idx += 128) {
        int r = idx / MD;
        int m = idx - r * MD;
        float push = (r == 0)      ? sigmoidf_(sh_fin[6 + m]) : stack[(r - 1) * MD + m];
        float pop  = (r == MS - 1) ? 0.0f                     : stack[(r + 1) * MD + m];
        out[OUT + H + idx] = fmaf(a0, push, a1 * pop);
    }
}

// ---------------------------------------------------------------------------
// Launch. Input order: inp, hidden0, stack, emb, w_ih, w_hh, b_ih, b_hh,
// w_y, b_y, w_n, b_n, w_a, b_a, w_sh, b_sh.
// Output: [output(4) | hidden(4096) | new_stack(312)] f32.
// ---------------------------------------------------------------------------
extern "C" void kernel_launch(void* const* d_in, const int* in_sizes, int n_in,
                              void* d_out, int out_size) {
    const int*   inp     = (const int*)  d_in[0];
    const float* hidden0 = (const float*)d_in[1];
    const float* stack   = (const float*)d_in[2];
    const float* emb     = (const float*)d_in[3];
    const float* w_ih    = (const float*)d_in[4];
    const float* w_hh    = (const float*)d_in[5];
    const float* b_ih    = (const float*)d_in[6];
    const float* b_hh    = (const float*)d_in[7];
    const float* w_y     = (const float*)d_in[8];
    const float* b_y     = (const float*)d_in[9];
    const float* w_n     = (const float*)d_in[10];
    const float* b_n     = (const float*)d_in[11];
    const float* w_a     = (const float*)d_in[12];
    const float* b_a     = (const float*)d_in[13];
    const float* w_sh    = (const float*)d_in[14];
    const float* b_sh    = (const float*)d_in[15];
    float* out = (float*)d_out;

    k_gru<<<GRID_GRU, 128>>>(w_hh, w_ih, b_ih, b_hh, emb, inp,
                             w_y, b_y, w_n, b_n, w_a, b_a, stack,
                             w_sh, b_sh, hidden0, out);
}

// round 10
// speedup vs baseline: 1.1242x; 1.0009x over previous
#include <cuda_runtime.h>
#include <math.h>
#include <stdint.h>

#define H 4096
#define V 4
#define MS 104
#define MD 3
#define OUT 4
#define GRID_GRU 1024   // H/4 blocks, 4 warps, 1 hidden unit per warp
#define B_RES 448       // blocks [0,B_RES): evict_last loads -> protected L2 set (~86 MB)

// scratch (device globals are the allowed scratch mechanism)
__device__ float g_dots[9];                 // zero at load; finale resets -> clean each replay
__device__ unsigned int g_count = 0;        // last-block detector; finale resets

__device__ __forceinline__ float sigmoidf_(float x) {
    return 1.0f / (1.0f + expf(-x));
}

// 32-byte evict_last load (sm_103a requires .v8.b32/.v4.b64 width for this hint)
__device__ __forceinline__ void ld_resident32B(const void* p, float4& lo, float4& hi) {
    unsigned long long a, b, c, d;
    asm("ld.global.L2::evict_last.v4.b64 {%0,%1,%2,%3}, [%4];"
        : "=l"(a), "=l"(b), "=l"(c), "=l"(d) : "l"(p));
    lo.x = __uint_as_float((unsigned)a);  lo.y = __uint_as_float((unsigned)(a >> 32));
    lo.z = __uint_as_float((unsigned)b);  lo.w = __uint_as_float((unsigned)(b >> 32));
    hi.x = __uint_as_float((unsigned)c);  hi.y = __uint_as_float((unsigned)(c >> 32));
    hi.z = __uint_as_float((unsigned)d);  hi.w = __uint_as_float((unsigned)(d >> 32));
}

__device__ __forceinline__ float dot4(float4 a, float4 b, float acc) {
    return fmaf(a.x, b.x, fmaf(a.y, b.y, fmaf(a.z, b.z, fmaf(a.w, b.w, acc))));
}

// resident mainloop: 32-byte evict_last loads, 16 iterations per row
__device__ __forceinline__ void gru_dots_resident(const float* __restrict__ wr,
                                                  const float* __restrict__ wz,
                                                  const float* __restrict__ wn,
                                                  const float4* __restrict__ s4,
                                                  int lane,
                                                  float& ar, float& az, float& an) {
    #pragma unroll 4
    for (int k = lane; k < H / 8; k += 32) {     // k indexes 32-byte chunks
        float4 hlo = s4[2 * k], hhi = s4[2 * k + 1];
        float4 rlo, rhi, zlo, zhi, nlo, nhi;
        ld_resident32B(wr + 8 * k, rlo, rhi);
        ld_resident32B(wz + 8 * k, zlo, zhi);
        ld_resident32B(wn + 8 * k, nlo, nhi);
        ar = dot4(rhi, hhi, dot4(rlo, hlo, ar));
        az = dot4(zhi, hhi, dot4(zlo, hlo, az));
        an = dot4(nhi, hhi, dot4(nlo, hlo, an));
    }
}

// streaming mainloop: __ldcs float4 (evict-first)
__device__ __forceinline__ void gru_dots_stream(const float4* __restrict__ wr,
                                                const float4* __restrict__ wz,
                                                const float4* __restrict__ wn,
                                                const float4* __restrict__ s4,
                                                int lane,
                                                float& ar, float& az, float& an) {
    #pragma unroll 4
    for (int k = lane; k < H / 4; k += 32) {
        float4 h4 = s4[k];
        ar = dot4(__ldcs(wr + k), h4, ar);
        az = dot4(__ldcs(wz + k), h4, az);
        an = dot4(__ldcs(wn + k), h4, an);
    }
}

// ---------------------------------------------------------------------------
// Single kernel, no cross-block sync for h_bar: every block computes the full
// h_bar itself (w_sh/b_sh/hidden0 are tiny and L2-hot), then the heavy matvec
// + GRU gates + fused heads + last-block finale.
// ---------------------------------------------------------------------------
__global__ void __launch_bounds__(128, 8)
k_gru(const float* __restrict__ w_hh,
      const float* __restrict__ w_ih,
      const float* __restrict__ b_ih,
      const float* __restrict__ b_hh,
      const float* __restrict__ emb,
      const int*   __restrict__ inp,
      const float* __restrict__ w_y,
      const float* __restrict__ b_y,
      const float* __restrict__ w_n,
      const float* __restrict__ b_n,
      const float* __restrict__ w_a,
      const float* __restrict__ b_a,
      const float* __restrict__ stack,
      const float* __restrict__ w_sh,
      const float* __restrict__ b_sh,
      const float* __restrict__ hidden0,
      float* __restrict__ out) {
    __shared__ float sh_hbar[H];
    __shared__ float sx[V];
    __shared__ float sh_h[4];
    __shared__ float sh_fin[12];   // [0..8]=dots+bias, [9]=a0, [10]=a1, [11]=is_last

    const int tid = threadIdx.x;

    // ---- per-block h_bar: 128 threads x 8 float4 outputs = 4096 elems ----
    {
        const float4* w4  = reinterpret_cast<const float4*>(w_sh);
        const float4* b4p = reinterpret_cast<const float4*>(b_sh);
        const float4* h4p = reinterpret_cast<const float4*>(hidden0);
        float4* swr = reinterpret_cast<float4*>(sh_hbar);
        const float s0 = stack[0], s1 = stack[1], s2 = stack[2];
        #pragma unroll
        for (int u = 0; u < 8; ++u) {
            const int t = tid + u * 128;       // float4 output index
            float4 a = w4[3 * t + 0];
            float4 b = w4[3 * t + 1];
            float4 c = w4[3 * t + 2];
            float4 bb = b4p[t];
            float4 h0 = h4p[t];
            float4 r;
            r.x = fmaf(a.x, s0, fmaf(a.y, s1, fmaf(a.z, s2, bb.x + h0.x)));
            r.y = fmaf(a.w, s0, fmaf(b.x, s1, fmaf(b.y, s2, bb.y + h0.y)));
            r.z = fmaf(b.z, s0, fmaf(b.w, s1, fmaf(c.x, s2, bb.z + h0.z)));
            r.w = fmaf(c.y, s0, fmaf(c.z, s1, fmaf(c.w, s2, bb.w + h0.w)));
            swr[t] = r;
        }
    }
    if (tid < V) sx[tid] = emb[inp[0] * V + tid];
    if (tid == 0) sh_fin[11] = 0.0f;
    __syncthreads();
    const float4* s4 = reinterpret_cast<const float4*>(sh_hbar);

    const int warp = tid >> 5;
    const int lane = tid & 31;
    const int i = blockIdx.x * 4 + warp;   // hidden unit

    const float* wr = w_hh + (size_t)i          * H;
    const float* wz = w_hh + (size_t)(i + H)    * H;
    const float* wn = w_hh + (size_t)(i + 2*H)  * H;

    float ar = 0.f, az = 0.f, an = 0.f;
    if (blockIdx.x < B_RES)
        gru_dots_resident(wr, wz, wn, s4, lane, ar, az, an);     // protected L2 set
    else
        gru_dots_stream(reinterpret_cast<const float4*>(wr),
                        reinterpret_cast<const float4*>(wz),
                        reinterpret_cast<const float4*>(wn),
                        s4, lane, ar, az, an);                   // streaming set

    #pragma unroll
    for (int o = 16; o > 0; o >>= 1) {
        ar += __shfl_xor_sync(0xFFFFFFFFu, ar, o);
        az += __shfl_xor_sync(0xFFFFFFFFu, az, o);
        an += __shfl_xor_sync(0xFFFFFFFFu, an, o);
    }

    if (lane == 0) {
        const float x0 = sx[0], x1 = sx[1], x2 = sx[2], x3 = sx[3];
        const float* wir = w_ih + (size_t)i * V;
        const float* wiz = w_ih + (size_t)(i + H) * V;
        const float* win = w_ih + (size_t)(i + 2*H) * V;
        float gir = fmaf(wir[0], x0, fmaf(wir[1], x1, fmaf(wir[2], x2, fmaf(wir[3], x3, b_ih[i]))));
        float giz = fmaf(wiz[0], x0, fmaf(wiz[1], x1, fmaf(wiz[2], x2, fmaf(wiz[3], x3, b_ih[i + H]))));
        float gin = fmaf(win[0], x0, fmaf(win[1], x1, fmaf(win[2], x2, fmaf(win[3], x3, b_ih[i + 2*H]))));

        float r = sigmoidf_(gir + ar + b_hh[i]);
        float z = sigmoidf_(giz + az + b_hh[i + H]);
        float n = tanhf(gin + (an + b_hh[i + 2*H]) * r);
        float hb = sh_hbar[i];
        float h = (1.0f - z) * n + z * hb;
        out[OUT + i] = h;
        sh_h[warp] = h;
    }
    __syncthreads();

    // head contributions: threads 0..8, one head each; rows i0..i0+3 are one float4
    if (tid < 9) {
        const int i0 = blockIdx.x * 4;
        const float* w = (tid < 4) ? (w_y + (size_t)tid * H)
                       : (tid < 6) ? (w_a + (size_t)(tid - 4) * H)
                                   : (w_n + (size_t)(tid - 6) * H);
        float4 wv = *reinterpret_cast<const float4*>(w + i0);
        float acc = fmaf(wv.x, sh_h[0], fmaf(wv.y, sh_h[1],
                    fmaf(wv.z, sh_h[2], wv.w * sh_h[3])));
        atomicAdd(&g_dots[tid], acc);
    }

    // last-block detection
    if (tid == 0) {
        __threadfence();
        unsigned int old = atomicAdd(&g_count, 1u);
        if (old == GRID_GRU - 1) sh_fin[11] = 1.0f;
    }
    __syncthreads();
    if (sh_fin[11] == 0.0f) return;

    // ---- finale (last block only) ----
    if (tid < 9) {
        float d = atomicExch(&g_dots[tid], 0.0f);   // read + reset for next replay
        float bias = (tid < 4) ? b_y[tid] : (tid < 6) ? b_a[tid - 4] : b_n[tid - 6];
        sh_fin[tid] = d + bias;
    }
    if (tid == 32) atomicExch(&g_count, 0u);        // reset detector
    __syncthreads();

    if (tid == 0) {
        out[0] = sigmoidf_(sh_fin[0]);
        out[1] = sigmoidf_(sh_fin[1]);
        out[2] = sigmoidf_(sh_fin[2]);
        out[3] = sigmoidf_(sh_fin[3]);
        float m  = fmaxf(sh_fin[4], sh_fin[5]);
        float e0 = expf(sh_fin[4] - m);
        float e1 = expf(sh_fin[5] - m);
        float inv = 1.0f / (e0 + e1);
        sh_fin[9]  = e0 * inv;
        sh_fin[10] = e1 * inv;
    }
    __syncthreads();

    const float a0 = sh_fin[9];
    const float a1 = sh_fin[10];
    for (int idx = tid; idx < MS * MD; idx += 128) {
        int r = idx / MD;
        int m = idx - r * MD;
        float push = (r == 0)      ? sigmoidf_(sh_fin[6 + m]) : stack[(r - 1) * MD + m];
        float pop  = (r == MS - 1) ? 0.0f                     : stack[(r + 1) * MD + m];
        out[OUT + H + idx] = fmaf(a0, push, a1 * pop);
    }
}

// ---------------------------------------------------------------------------
// Launch. Input order: inp, hidden0, stack, emb, w_ih, w_hh, b_ih, b_hh,
// w_y, b_y, w_n, b_n, w_a, b_a, w_sh, b_sh.
// Output: [output(4) | hidden(4096) | new_stack(312)] f32.
// ---------------------------------------------------------------------------
extern "C" void kernel_launch(void* const* d_in, const int* in_sizes, int n_in,
                              void* d_out, int out_size) {
    const int*   inp     = (const int*)  d_in[0];
    const float* hidden0 = (const float*)d_in[1];
    const float* stack   = (const float*)d_in[2];
    const float* emb     = (const float*)d_in[3];
    const float* w_ih    = (const float*)d_in[4];
    const float* w_hh    = (const float*)d_in[5];
    const float* b_ih    = (const float*)d_in[6];
    const float* b_hh    = (const float*)d_in[7];
    const float* w_y     = (const float*)d_in[8];
    const float* b_y     = (const float*)d_in[9];
    const float* w_n     = (const float*)d_in[10];
    const float* b_n     = (const float*)d_in[11];
    const float* w_a     = (const float*)d_in[12];
    const float* b_a     = (const float*)d_in[13];
    const float* w_sh    = (const float*)d_in[14];
    const float* b_sh    = (const float*)d_in[15];
    float* out = (float*)d_out;

    k_gru<<<GRID_GRU, 128>>>(w_hh, w_ih, b_ih, b_hh, emb, inp,
                             w_y, b_y, w_n, b_n, w_a, b_a, stack,
                             w_sh, b_sh, hidden0, out);
}